// round 1
// baseline (speedup 1.0000x reference)
#include <cuda_runtime.h>

// entmax-1.5 attention, B=8 H=8 S=1024 D=64, fp32.
// One CTA per (batch*head, 32-query tile). Scores tile (32x1024 fp32) resident
// in shared memory across both GEMM phases; entmax tau found by bisection
// (exact root of sum(max(x/2 - tau,0)^2) = 1, same tau* as the sort algorithm).

#define SEQ   1024
#define DH    64
#define QT    32
#define KTILE 128
#define NTHR  256
#define BISECT_ITERS 30

// dynamic smem layout (floats):
//   sc : QT * SEQ              = 32768   (scores / probabilities tile)
//   Ks : DH * (KTILE+1)        = 8256    (K tile, transposed, padded; reused as V tile 64x64)
//   Qs : QT * DH               = 2048
// total 43072 floats = 172288 bytes
#define SMEM_FLOATS (QT*SEQ + DH*(KTILE+1) + QT*DH)

__global__ void __launch_bounds__(NTHR, 1)
attn_entmax15_kernel(const float* __restrict__ qg,
                     const float* __restrict__ kg,
                     const float* __restrict__ vg,
                     float* __restrict__ og)
{
    extern __shared__ float sm[];
    float* sc = sm;                       // [QT][SEQ]
    float* Ks = sm + QT * SEQ;            // [DH][KTILE+1] transposed K (also V tile [64][64])
    float* Qs = Ks + DH * (KTILE + 1);    // [QT][DH]

    const int tid  = threadIdx.x;
    const int lane = tid & 31;
    const int wid  = tid >> 5;            // 8 warps
    const int qt   = blockIdx.x;          // 0..31 query tile
    const int bh   = blockIdx.y;          // 0..63 batch*head

    const float* Qg = qg + (size_t)bh * SEQ * DH + (size_t)qt * QT * DH;
    const float* Kg = kg + (size_t)bh * SEQ * DH;
    const float* Vg = vg + (size_t)bh * SEQ * DH;
    float*       Og = og + (size_t)bh * SEQ * DH + (size_t)qt * QT * DH;

    // ---- load Q tile (2048 floats, coalesced) ----
#pragma unroll
    for (int i = 0; i < (QT * DH) / NTHR; i++) {
        int idx = i * NTHR + tid;
        Qs[idx] = Qg[idx];
    }

    const int qr = wid * 4;   // each warp owns 4 query rows

    // =========================== Phase 1: S = Q K^T =========================
    // thread tile: 4 q-rows x 4 k-cols (k = lane, lane+32, lane+64, lane+96)
    for (int kt = 0; kt < SEQ / KTILE; kt++) {
        __syncthreads();   // also covers Qs load on first iteration
        // load K tile transposed into Ks[d][k], pad stride KTILE+1 (conflict-free)
#pragma unroll
        for (int i = 0; i < (KTILE * DH) / NTHR; i++) {
            int idx = i * NTHR + tid;
            int r = idx >> 6;        // key row within tile, 0..127
            int c = idx & 63;        // d
            Ks[c * (KTILE + 1) + r] = Kg[(size_t)(kt * KTILE + r) * DH + c];
        }
        __syncthreads();

        float acc[4][4];
#pragma unroll
        for (int i = 0; i < 4; i++)
#pragma unroll
            for (int j = 0; j < 4; j++) acc[i][j] = 0.f;

#pragma unroll 4
        for (int d = 0; d < DH; d++) {
            float qv[4], kv[4];
#pragma unroll
            for (int i = 0; i < 4; i++) qv[i] = Qs[(qr + i) * DH + d];
#pragma unroll
            for (int j = 0; j < 4; j++) kv[j] = Ks[d * (KTILE + 1) + lane + 32 * j];
#pragma unroll
            for (int i = 0; i < 4; i++)
#pragma unroll
                for (int j = 0; j < 4; j++)
                    acc[i][j] = fmaf(qv[i], kv[j], acc[i][j]);
        }

#pragma unroll
        for (int i = 0; i < 4; i++)
#pragma unroll
            for (int j = 0; j < 4; j++)
                sc[(qr + i) * SEQ + kt * KTILE + lane + 32 * j] = acc[i][j];
    }
    __syncthreads();

    // ======================= Phase 2: entmax-1.5 per row ====================
    // x = score / sqrt(D) / 2 = score * 0.0625 ; shift by max ; bisect tau in
    // [-1, 0] s.t. sum(max(x - tau, 0)^2) == 1 ; p = max(x - tau, 0)^2.
    for (int rr = 0; rr < 4; rr++) {
        const int row = qr + rr;
        float x[32];
        float m = -1e30f;
#pragma unroll
        for (int j = 0; j < 32; j++) {
            x[j] = sc[row * SEQ + j * 32 + lane] * 0.0625f;
            m = fmaxf(m, x[j]);
        }
#pragma unroll
        for (int o = 16; o; o >>= 1) m = fmaxf(m, __shfl_xor_sync(0xffffffffu, m, o));
#pragma unroll
        for (int j = 0; j < 32; j++) x[j] -= m;

        float lo = -1.f, hi = 0.f;
        for (int it = 0; it < BISECT_ITERS; it++) {
            float tau = 0.5f * (lo + hi);
            float s = 0.f;
#pragma unroll
            for (int j = 0; j < 32; j++) {
                float t = fmaxf(x[j] - tau, 0.f);
                s = fmaf(t, t, s);
            }
#pragma unroll
            for (int o = 16; o; o >>= 1) s += __shfl_xor_sync(0xffffffffu, s, o);
            if (s > 1.f) lo = tau; else hi = tau;
        }
        float tau = 0.5f * (lo + hi);
#pragma unroll
        for (int j = 0; j < 32; j++) {
            float t = fmaxf(x[j] - tau, 0.f);
            sc[row * SEQ + j * 32 + lane] = t * t;
        }
    }
    __syncthreads();

    // =========================== Phase 3: O = P V ===========================
    // thread tile: 4 q-rows x 2 d-cols (d = lane, lane+32). V tiles of 64 rows.
    float* Vs = Ks;   // reuse, [64][64]
    float oacc[4][2];
#pragma unroll
    for (int i = 0; i < 4; i++) { oacc[i][0] = 0.f; oacc[i][1] = 0.f; }

    for (int vt = 0; vt < SEQ / 64; vt++) {
        __syncthreads();   // previous V tile fully consumed
#pragma unroll
        for (int i = 0; i < (64 * DH) / NTHR; i++) {
            int idx = i * NTHR + tid;
            Vs[idx] = Vg[(size_t)vt * 64 * DH + idx];
        }
        __syncthreads();

#pragma unroll 4
        for (int kk = 0; kk < 64; kk++) {
            float v0 = Vs[kk * DH + lane];
            float v1 = Vs[kk * DH + lane + 32];
#pragma unroll
            for (int i = 0; i < 4; i++) {
                float a = sc[(qr + i) * SEQ + vt * 64 + kk];
                oacc[i][0] = fmaf(a, v0, oacc[i][0]);
                oacc[i][1] = fmaf(a, v1, oacc[i][1]);
            }
        }
    }

#pragma unroll
    for (int i = 0; i < 4; i++) {
        Og[(qr + i) * DH + lane]      = oacc[i][0];
        Og[(qr + i) * DH + lane + 32] = oacc[i][1];
    }
}

extern "C" void kernel_launch(void* const* d_in, const int* in_sizes, int n_in,
                              void* d_out, int out_size)
{
    const float* q = (const float*)d_in[0];
    const float* k = (const float*)d_in[1];
    const float* v = (const float*)d_in[2];
    float* out = (float*)d_out;

    const int smem_bytes = SMEM_FLOATS * sizeof(float);   // 172288
    cudaFuncSetAttribute(attn_entmax15_kernel,
                         cudaFuncAttributeMaxDynamicSharedMemorySize, smem_bytes);

    dim3 grid(SEQ / QT, 8 * 8);   // (32 q-tiles, 64 batch*head)
    attn_entmax15_kernel<<<grid, NTHR, smem_bytes>>>(q, k, v, out);
}

// round 2
// speedup vs baseline: 1.0006x; 1.0006x over previous
#include <cuda_runtime.h>

// entmax-1.5 attention, B=8 H=8 S=1024 D=64, fp32.
// One CTA per (batch*head, 32-query tile). Scores tile (32x1024 fp32) resident
// in shared memory across both GEMM phases; entmax tau found by bisection
// (exact root of sum(max(x/2 - tau,0)^2) = 1, same tau* as the sort algorithm).

#define SEQ   1024
#define DH    64
#define QT    32
#define KTILE 128
#define NTHR  256
#define BISECT_ITERS 30

// dynamic smem layout (floats):
//   sc : QT * SEQ              = 32768   (scores / probabilities tile)
//   Ks : DH * (KTILE+1)        = 8256    (K tile, transposed, padded; reused as V tile 64x64)
//   Qs : QT * DH               = 2048
// total 43072 floats = 172288 bytes
#define SMEM_FLOATS (QT*SEQ + DH*(KTILE+1) + QT*DH)

__global__ void __launch_bounds__(NTHR, 1)
attn_entmax15_kernel(const float* __restrict__ qg,
                     const float* __restrict__ kg,
                     const float* __restrict__ vg,
                     float* __restrict__ og)
{
    extern __shared__ float sm[];
    float* sc = sm;                       // [QT][SEQ]
    float* Ks = sm + QT * SEQ;            // [DH][KTILE+1] transposed K (also V tile [64][64])
    float* Qs = Ks + DH * (KTILE + 1);    // [QT][DH]

    const int tid  = threadIdx.x;
    const int lane = tid & 31;
    const int wid  = tid >> 5;            // 8 warps
    const int qt   = blockIdx.x;          // 0..31 query tile
    const int bh   = blockIdx.y;          // 0..63 batch*head

    const float* Qg = qg + (size_t)bh * SEQ * DH + (size_t)qt * QT * DH;
    const float* Kg = kg + (size_t)bh * SEQ * DH;
    const float* Vg = vg + (size_t)bh * SEQ * DH;
    float*       Og = og + (size_t)bh * SEQ * DH + (size_t)qt * QT * DH;

    // ---- load Q tile (2048 floats, coalesced) ----
#pragma unroll
    for (int i = 0; i < (QT * DH) / NTHR; i++) {
        int idx = i * NTHR + tid;
        Qs[idx] = Qg[idx];
    }

    const int qr = wid * 4;   // each warp owns 4 query rows

    // =========================== Phase 1: S = Q K^T =========================
    // thread tile: 4 q-rows x 4 k-cols (k = lane, lane+32, lane+64, lane+96)
    for (int kt = 0; kt < SEQ / KTILE; kt++) {
        __syncthreads();   // also covers Qs load on first iteration
        // load K tile transposed into Ks[d][k], pad stride KTILE+1 (conflict-free)
#pragma unroll
        for (int i = 0; i < (KTILE * DH) / NTHR; i++) {
            int idx = i * NTHR + tid;
            int r = idx >> 6;        // key row within tile, 0..127
            int c = idx & 63;        // d
            Ks[c * (KTILE + 1) + r] = Kg[(size_t)(kt * KTILE + r) * DH + c];
        }
        __syncthreads();

        float acc[4][4];
#pragma unroll
        for (int i = 0; i < 4; i++)
#pragma unroll
            for (int j = 0; j < 4; j++) acc[i][j] = 0.f;

#pragma unroll 4
        for (int d = 0; d < DH; d++) {
            float qv[4], kv[4];
#pragma unroll
            for (int i = 0; i < 4; i++) qv[i] = Qs[(qr + i) * DH + d];
#pragma unroll
            for (int j = 0; j < 4; j++) kv[j] = Ks[d * (KTILE + 1) + lane + 32 * j];
#pragma unroll
            for (int i = 0; i < 4; i++)
#pragma unroll
                for (int j = 0; j < 4; j++)
                    acc[i][j] = fmaf(qv[i], kv[j], acc[i][j]);
        }

#pragma unroll
        for (int i = 0; i < 4; i++)
#pragma unroll
            for (int j = 0; j < 4; j++)
                sc[(qr + i) * SEQ + kt * KTILE + lane + 32 * j] = acc[i][j];
    }
    __syncthreads();

    // ======================= Phase 2: entmax-1.5 per row ====================
    // x = score / sqrt(D) / 2 = score * 0.0625 ; shift by max ; bisect tau in
    // [-1, 0] s.t. sum(max(x - tau, 0)^2) == 1 ; p = max(x - tau, 0)^2.
    for (int rr = 0; rr < 4; rr++) {
        const int row = qr + rr;
        float x[32];
        float m = -1e30f;
#pragma unroll
        for (int j = 0; j < 32; j++) {
            x[j] = sc[row * SEQ + j * 32 + lane] * 0.0625f;
            m = fmaxf(m, x[j]);
        }
#pragma unroll
        for (int o = 16; o; o >>= 1) m = fmaxf(m, __shfl_xor_sync(0xffffffffu, m, o));
#pragma unroll
        for (int j = 0; j < 32; j++) x[j] -= m;

        float lo = -1.f, hi = 0.f;
        for (int it = 0; it < BISECT_ITERS; it++) {
            float tau = 0.5f * (lo + hi);
            float s = 0.f;
#pragma unroll
            for (int j = 0; j < 32; j++) {
                float t = fmaxf(x[j] - tau, 0.f);
                s = fmaf(t, t, s);
            }
#pragma unroll
            for (int o = 16; o; o >>= 1) s += __shfl_xor_sync(0xffffffffu, s, o);
            if (s > 1.f) lo = tau; else hi = tau;
        }
        float tau = 0.5f * (lo + hi);
#pragma unroll
        for (int j = 0; j < 32; j++) {
            float t = fmaxf(x[j] - tau, 0.f);
            sc[row * SEQ + j * 32 + lane] = t * t;
        }
    }
    __syncthreads();

    // =========================== Phase 3: O = P V ===========================
    // thread tile: 4 q-rows x 2 d-cols (d = lane, lane+32). V tiles of 64 rows.
    float* Vs = Ks;   // reuse, [64][64]
    float oacc[4][2];
#pragma unroll
    for (int i = 0; i < 4; i++) { oacc[i][0] = 0.f; oacc[i][1] = 0.f; }

    for (int vt = 0; vt < SEQ / 64; vt++) {
        __syncthreads();   // previous V tile fully consumed
#pragma unroll
        for (int i = 0; i < (64 * DH) / NTHR; i++) {
            int idx = i * NTHR + tid;
            Vs[idx] = Vg[(size_t)vt * 64 * DH + idx];
        }
        __syncthreads();

#pragma unroll 4
        for (int kk = 0; kk < 64; kk++) {
            float v0 = Vs[kk * DH + lane];
            float v1 = Vs[kk * DH + lane + 32];
#pragma unroll
            for (int i = 0; i < 4; i++) {
                float a = sc[(qr + i) * SEQ + vt * 64 + kk];
                oacc[i][0] = fmaf(a, v0, oacc[i][0]);
                oacc[i][1] = fmaf(a, v1, oacc[i][1]);
            }
        }
    }

#pragma unroll
    for (int i = 0; i < 4; i++) {
        Og[(qr + i) * DH + lane]      = oacc[i][0];
        Og[(qr + i) * DH + lane + 32] = oacc[i][1];
    }
}

extern "C" void kernel_launch(void* const* d_in, const int* in_sizes, int n_in,
                              void* d_out, int out_size)
{
    const float* q = (const float*)d_in[0];
    const float* k = (const float*)d_in[1];
    const float* v = (const float*)d_in[2];
    float* out = (float*)d_out;

    const int smem_bytes = SMEM_FLOATS * sizeof(float);   // 172288
    cudaFuncSetAttribute(attn_entmax15_kernel,
                         cudaFuncAttributeMaxDynamicSharedMemorySize, smem_bytes);

    dim3 grid(SEQ / QT, 8 * 8);   // (32 q-tiles, 64 batch*head)
    attn_entmax15_kernel<<<grid, NTHR, smem_bytes>>>(q, k, v, out);
}

// round 3
// speedup vs baseline: 1.0009x; 1.0004x over previous
#include <cuda_runtime.h>

// entmax-1.5 attention, B=8 H=8 S=1024 D=64, fp32.
// One CTA per (batch*head, 32-query tile). Scores tile (32x1024 fp32) resident
// in shared memory across both GEMM phases; entmax tau found by bisection
// (exact root of sum(max(x/2 - tau,0)^2) = 1, same tau* as the sort algorithm).

#define SEQ   1024
#define DH    64
#define QT    32
#define KTILE 128
#define NTHR  256
#define BISECT_ITERS 30

// dynamic smem layout (floats):
//   sc : QT * SEQ              = 32768   (scores / probabilities tile)
//   Ks : DH * (KTILE+1)        = 8256    (K tile, transposed, padded; reused as V tile 64x64)
//   Qs : QT * DH               = 2048
// total 43072 floats = 172288 bytes
#define SMEM_FLOATS (QT*SEQ + DH*(KTILE+1) + QT*DH)

__global__ void __launch_bounds__(NTHR, 1)
attn_entmax15_kernel(const float* __restrict__ qg,
                     const float* __restrict__ kg,
                     const float* __restrict__ vg,
                     float* __restrict__ og)
{
    extern __shared__ float sm[];
    float* sc = sm;                       // [QT][SEQ]
    float* Ks = sm + QT * SEQ;            // [DH][KTILE+1] transposed K (also V tile [64][64])
    float* Qs = Ks + DH * (KTILE + 1);    // [QT][DH]

    const int tid  = threadIdx.x;
    const int lane = tid & 31;
    const int wid  = tid >> 5;            // 8 warps
    const int qt   = blockIdx.x;          // 0..31 query tile
    const int bh   = blockIdx.y;          // 0..63 batch*head

    const float* Qg = qg + (size_t)bh * SEQ * DH + (size_t)qt * QT * DH;
    const float* Kg = kg + (size_t)bh * SEQ * DH;
    const float* Vg = vg + (size_t)bh * SEQ * DH;
    float*       Og = og + (size_t)bh * SEQ * DH + (size_t)qt * QT * DH;

    // ---- load Q tile (2048 floats, coalesced) ----
#pragma unroll
    for (int i = 0; i < (QT * DH) / NTHR; i++) {
        int idx = i * NTHR + tid;
        Qs[idx] = Qg[idx];
    }

    const int qr = wid * 4;   // each warp owns 4 query rows

    // =========================== Phase 1: S = Q K^T =========================
    // thread tile: 4 q-rows x 4 k-cols (k = lane, lane+32, lane+64, lane+96)
    for (int kt = 0; kt < SEQ / KTILE; kt++) {
        __syncthreads();   // also covers Qs load on first iteration
        // load K tile transposed into Ks[d][k], pad stride KTILE+1 (conflict-free)
#pragma unroll
        for (int i = 0; i < (KTILE * DH) / NTHR; i++) {
            int idx = i * NTHR + tid;
            int r = idx >> 6;        // key row within tile, 0..127
            int c = idx & 63;        // d
            Ks[c * (KTILE + 1) + r] = Kg[(size_t)(kt * KTILE + r) * DH + c];
        }
        __syncthreads();

        float acc[4][4];
#pragma unroll
        for (int i = 0; i < 4; i++)
#pragma unroll
            for (int j = 0; j < 4; j++) acc[i][j] = 0.f;

#pragma unroll 4
        for (int d = 0; d < DH; d++) {
            float qv[4], kv[4];
#pragma unroll
            for (int i = 0; i < 4; i++) qv[i] = Qs[(qr + i) * DH + d];
#pragma unroll
            for (int j = 0; j < 4; j++) kv[j] = Ks[d * (KTILE + 1) + lane + 32 * j];
#pragma unroll
            for (int i = 0; i < 4; i++)
#pragma unroll
                for (int j = 0; j < 4; j++)
                    acc[i][j] = fmaf(qv[i], kv[j], acc[i][j]);
        }

#pragma unroll
        for (int i = 0; i < 4; i++)
#pragma unroll
            for (int j = 0; j < 4; j++)
                sc[(qr + i) * SEQ + kt * KTILE + lane + 32 * j] = acc[i][j];
    }
    __syncthreads();

    // ======================= Phase 2: entmax-1.5 per row ====================
    // x = score / sqrt(D) / 2 = score * 0.0625 ; shift by max ; bisect tau in
    // [-1, 0] s.t. sum(max(x - tau, 0)^2) == 1 ; p = max(x - tau, 0)^2.
    for (int rr = 0; rr < 4; rr++) {
        const int row = qr + rr;
        float x[32];
        float m = -1e30f;
#pragma unroll
        for (int j = 0; j < 32; j++) {
            x[j] = sc[row * SEQ + j * 32 + lane] * 0.0625f;
            m = fmaxf(m, x[j]);
        }
#pragma unroll
        for (int o = 16; o; o >>= 1) m = fmaxf(m, __shfl_xor_sync(0xffffffffu, m, o));
#pragma unroll
        for (int j = 0; j < 32; j++) x[j] -= m;

        float lo = -1.f, hi = 0.f;
        for (int it = 0; it < BISECT_ITERS; it++) {
            float tau = 0.5f * (lo + hi);
            float s = 0.f;
#pragma unroll
            for (int j = 0; j < 32; j++) {
                float t = fmaxf(x[j] - tau, 0.f);
                s = fmaf(t, t, s);
            }
#pragma unroll
            for (int o = 16; o; o >>= 1) s += __shfl_xor_sync(0xffffffffu, s, o);
            if (s > 1.f) lo = tau; else hi = tau;
        }
        float tau = 0.5f * (lo + hi);
#pragma unroll
        for (int j = 0; j < 32; j++) {
            float t = fmaxf(x[j] - tau, 0.f);
            sc[row * SEQ + j * 32 + lane] = t * t;
        }
    }
    __syncthreads();

    // =========================== Phase 3: O = P V ===========================
    // thread tile: 4 q-rows x 2 d-cols (d = lane, lane+32). V tiles of 64 rows.
    float* Vs = Ks;   // reuse, [64][64]
    float oacc[4][2];
#pragma unroll
    for (int i = 0; i < 4; i++) { oacc[i][0] = 0.f; oacc[i][1] = 0.f; }

    for (int vt = 0; vt < SEQ / 64; vt++) {
        __syncthreads();   // previous V tile fully consumed
#pragma unroll
        for (int i = 0; i < (64 * DH) / NTHR; i++) {
            int idx = i * NTHR + tid;
            Vs[idx] = Vg[(size_t)vt * 64 * DH + idx];
        }
        __syncthreads();

#pragma unroll 4
        for (int kk = 0; kk < 64; kk++) {
            float v0 = Vs[kk * DH + lane];
            float v1 = Vs[kk * DH + lane + 32];
#pragma unroll
            for (int i = 0; i < 4; i++) {
                float a = sc[(qr + i) * SEQ + vt * 64 + kk];
                oacc[i][0] = fmaf(a, v0, oacc[i][0]);
                oacc[i][1] = fmaf(a, v1, oacc[i][1]);
            }
        }
    }

#pragma unroll
    for (int i = 0; i < 4; i++) {
        Og[(qr + i) * DH + lane]      = oacc[i][0];
        Og[(qr + i) * DH + lane + 32] = oacc[i][1];
    }
}

extern "C" void kernel_launch(void* const* d_in, const int* in_sizes, int n_in,
                              void* d_out, int out_size)
{
    const float* q = (const float*)d_in[0];
    const float* k = (const float*)d_in[1];
    const float* v = (const float*)d_in[2];
    float* out = (float*)d_out;

    const int smem_bytes = SMEM_FLOATS * sizeof(float);   // 172288
    cudaFuncSetAttribute(attn_entmax15_kernel,
                         cudaFuncAttributeMaxDynamicSharedMemorySize, smem_bytes);

    dim3 grid(SEQ / QT, 8 * 8);   // (32 q-tiles, 64 batch*head)
    attn_entmax15_kernel<<<grid, NTHR, smem_bytes>>>(q, k, v, out);
}

// round 4
// speedup vs baseline: 1.1556x; 1.1545x over previous
#include <cuda_runtime.h>

// entmax-1.5 attention, B=8 H=8 S=1024 D=64, fp32.
// 512 threads/CTA, f32x2-packed FMAs, scores stored k-major in smem,
// Newton iteration for the entmax threshold.

#define SEQ   1024
#define DH    64
#define QT    32
#define NTHR  512
#define SCS   34        // sc row stride (floats) over k rows: [1024][34]
#define KSS   258       // Ks row stride (floats) per d: [64][258]
#define KTILE 256
#define VTILE 128
#define NEWTON 10

typedef unsigned long long u64;

#define SC_FLOATS (SEQ * SCS)        // 34816
#define KS_FLOATS (DH * KSS)         // 16512 (also holds Vdup: 128*64*2 = 16384)
#define QD_FLOATS (QT * DH * 2)      // 4096
#define SMEM_BYTES ((SC_FLOATS + KS_FLOATS + QD_FLOATS) * 4)   // 221696

__device__ __forceinline__ u64 fma2(u64 a, u64 b, u64 c) {
    u64 d;
    asm("fma.rn.f32x2 %0, %1, %2, %3;" : "=l"(d) : "l"(a), "l"(b), "l"(c));
    return d;
}
__device__ __forceinline__ u64 add2(u64 a, u64 b) {
    u64 d;
    asm("add.rn.f32x2 %0, %1, %2;" : "=l"(d) : "l"(a), "l"(b));
    return d;
}

__global__ void __launch_bounds__(NTHR, 1)
attn_entmax15_kernel(const float* __restrict__ qg,
                     const float* __restrict__ kg,
                     const float* __restrict__ vg,
                     float* __restrict__ og)
{
    extern __shared__ float sm[];
    float* sc  = sm;                       // [1024 k][SCS]  scores, k-major
    float* Ks  = sm + SC_FLOATS;           // [64 d][KSS]    K tile transposed (reused as Vdup)
    float2* Qd = (float2*)(Ks + KS_FLOATS);// [64 d][32 q]   Q duplicated (splat pairs)

    const int tid  = threadIdx.x;
    const int lane = tid & 31;
    const int wid  = tid >> 5;             // 0..15
    const int qg2  = wid >> 2;             // q-group 0..3 (8 q rows each)
    const int sub  = wid & 3;              // k/d sub-slot 0..3
    const int qt   = blockIdx.x;           // 0..31
    const int bh   = blockIdx.y;           // 0..63

    const float* Qg = qg + (size_t)bh * SEQ * DH + (size_t)qt * QT * DH;
    const float* Kg = kg + (size_t)bh * SEQ * DH;
    const float* Vg = vg + (size_t)bh * SEQ * DH;
    float*       Og = og + (size_t)bh * SEQ * DH + (size_t)qt * QT * DH;

    // ---- load Q, duplicated layout Qd[d][q] = (Q[q][d], Q[q][d]) ----
#pragma unroll
    for (int i = 0; i < (QT * DH) / NTHR; i++) {
        int idx = i * NTHR + tid;
        int q = idx >> 6, d = idx & 63;
        float v = Qg[idx];
        Qd[d * QT + q] = make_float2(v, v);
    }

    // ======================= Phase 1: S = Q K^T (f32x2 over k-pairs) ========
    // warp (qg2, sub): 8 q rows x 64 k cols; thread: 8 q x 1 k-pair (lane*2).
    const u64* Qd64 = (const u64*)Qd;
    for (int kt = 0; kt < SEQ / KTILE; kt++) {
        __syncthreads();
        // K tile transposed: Ks[d][k], stride KSS (even -> aligned LDS.64)
#pragma unroll
        for (int i = 0; i < (KTILE * DH) / NTHR; i++) {
            int idx = i * NTHR + tid;
            int r = idx >> 6, c = idx & 63;
            Ks[c * KSS + r] = Kg[(size_t)kt * (KTILE * DH) + idx];
        }
        __syncthreads();

        const int kloc = sub * 64 + lane * 2;       // k within tile
        u64 acc[8];
#pragma unroll
        for (int i = 0; i < 8; i++) acc[i] = 0ull;

#pragma unroll 8
        for (int d = 0; d < DH; d++) {
            u64 kv = *(const u64*)&Ks[d * KSS + kloc];
#pragma unroll
            for (int i = 0; i < 8; i++)
                acc[i] = fma2(Qd64[d * QT + qg2 * 8 + i], kv, acc[i]);
        }

        const int kb = kt * KTILE + kloc;
#pragma unroll
        for (int i = 0; i < 8; i++) {
            float2 a = *(float2*)&acc[i];
            int q = qg2 * 8 + i;
            sc[kb * SCS + q]       = a.x;
            sc[(kb + 1) * SCS + q] = a.y;
        }
    }
    __syncthreads();

    // ======================= Phase 2: entmax-1.5 (Newton) ===================
    // x = score * 0.0625 (1/sqrt(64)/2), shift by max; Newton on
    // f(tau)=sum(max(x-tau,0)^2)-1 from tau=-1 (monotone, convex-safe).
    for (int rr = 0; rr < 2; rr++) {
        const int row = wid * 2 + rr;
        float x[32];
        float m = -1e30f;
#pragma unroll
        for (int j = 0; j < 32; j++) {
            x[j] = sc[(j * 32 + lane) * SCS + row] * 0.0625f;
            m = fmaxf(m, x[j]);
        }
#pragma unroll
        for (int o = 16; o; o >>= 1) m = fmaxf(m, __shfl_xor_sync(0xffffffffu, m, o));
#pragma unroll
        for (int j = 0; j < 32; j++) x[j] -= m;

        float tau = -1.0f;
#pragma unroll 1
        for (int it = 0; it < NEWTON; it++) {
            float s = 0.f, r = 0.f;
#pragma unroll
            for (int j = 0; j < 32; j++) {
                float t = fmaxf(x[j] - tau, 0.f);
                s = fmaf(t, t, s);
                r += t;
            }
#pragma unroll
            for (int o = 16; o; o >>= 1) {
                s += __shfl_xor_sync(0xffffffffu, s, o);
                r += __shfl_xor_sync(0xffffffffu, r, o);
            }
            tau += (s - 1.0f) / (2.0f * r);
        }
#pragma unroll
        for (int j = 0; j < 32; j++) {
            float t = fmaxf(x[j] - tau, 0.f);
            sc[(j * 32 + lane) * SCS + row] = t * t;
        }
    }

    // ======================= Phase 3: O = P V (f32x2 over q-pairs) ==========
    // warp (qg2, sub): thread d = sub*16 + (lane&15); half-warps interleave k.
    const int d3   = sub * 16 + (lane & 15);
    const int koff = lane >> 4;
    u64* Vd64 = (u64*)Ks;                   // Vdup[kloc][d] = (v, v), reuse K region
    u64 acc3[4];
#pragma unroll
    for (int i = 0; i < 4; i++) acc3[i] = 0ull;

    for (int vt = 0; vt < SEQ / VTILE; vt++) {
        __syncthreads();
#pragma unroll
        for (int i = 0; i < (VTILE * DH) / NTHR; i++) {
            int idx = i * NTHR + tid;
            float v = Vg[(size_t)vt * (VTILE * DH) + idx];
            ((float2*)Vd64)[idx] = make_float2(v, v);
        }
        __syncthreads();

#pragma unroll 4
        for (int kk = 0; kk < VTILE; kk += 2) {
            int kl = kk + koff;
            int kglob = vt * VTILE + kl;
            u64 vv = Vd64[kl * DH + d3];
            const float* base = &sc[kglob * SCS + qg2 * 8];
#pragma unroll
            for (int i = 0; i < 4; i++)
                acc3[i] = fma2(*(const u64*)(base + 2 * i), vv, acc3[i]);
        }
    }

    // combine the two half-warp k-partials, then write O
#pragma unroll
    for (int i = 0; i < 4; i++) {
        u64 other = __shfl_xor_sync(0xffffffffu, acc3[i], 16);
        acc3[i] = add2(acc3[i], other);
    }
    if (lane < 16) {
#pragma unroll
        for (int i = 0; i < 4; i++) {
            float2 a = *(float2*)&acc3[i];
            Og[(qg2 * 8 + 2 * i) * DH + d3]     = a.x;
            Og[(qg2 * 8 + 2 * i + 1) * DH + d3] = a.y;
        }
    }
}

extern "C" void kernel_launch(void* const* d_in, const int* in_sizes, int n_in,
                              void* d_out, int out_size)
{
    const float* q = (const float*)d_in[0];
    const float* k = (const float*)d_in[1];
    const float* v = (const float*)d_in[2];
    float* out = (float*)d_out;

    cudaFuncSetAttribute(attn_entmax15_kernel,
                         cudaFuncAttributeMaxDynamicSharedMemorySize, SMEM_BYTES);

    dim3 grid(SEQ / QT, 8 * 8);
    attn_entmax15_kernel<<<grid, NTHR, SMEM_BYTES>>>(q, k, v, out);
}

// round 5
// speedup vs baseline: 1.3888x; 1.2018x over previous
#include <cuda_runtime.h>

// entmax-1.5 attention, B=8 H=8 S=1024 D=64, fp32.
// Register-blocked f32x2 outer-product GEMMs; scores k-major in smem;
// Newton iteration for the entmax threshold.

#define SEQ   1024
#define DH    64
#define QT    32
#define NTHR  512
#define SCS   34      // sc float stride per k-row
#define KTILE 256
#define KDS   66      // Kt float stride per k-row
#define VTILE 128
#define VDS   68      // Vdup u64 stride per k-row (136 floats)
#define QPS   34      // Qps float stride per d
#define OSS   66      // Osm float stride per q-row
#define NEWTON 10

typedef unsigned long long u64;

#define SC_FL (SEQ * SCS)                 // 34816
#define KV_FL (VTILE * VDS * 2)           // 17408 (>= KTILE*KDS = 16896)
#define QO_FL (DH * QPS)                  // 2176  (>= 32*OSS = 2112)
#define SMEM_BYTES ((SC_FL + KV_FL + QO_FL) * 4)   // 217600

__device__ __forceinline__ u64 fma2(u64 a, u64 b, u64 c) {
    u64 d;
    asm("fma.rn.f32x2 %0, %1, %2, %3;" : "=l"(d) : "l"(a), "l"(b), "l"(c));
    return d;
}
__device__ __forceinline__ u64 add2(u64 a, u64 b) {
    u64 d;
    asm("add.rn.f32x2 %0, %1, %2;" : "=l"(d) : "l"(a), "l"(b));
    return d;
}
__device__ __forceinline__ u64 dup2(float v) {
    u64 d;
    asm("mov.b64 %0, {%1, %1};" : "=l"(d) : "f"(v));
    return d;
}

__global__ void __launch_bounds__(NTHR, 1)
attn_entmax15_kernel(const float* __restrict__ qg,
                     const float* __restrict__ kg,
                     const float* __restrict__ vg,
                     float* __restrict__ og)
{
    extern __shared__ float sm[];
    float* sc = sm;                 // [1024 k][SCS]  scores (k-major, q contiguous)
    float* KV = sm + SC_FL;         // Kt [256][KDS] in phase 1; Vdup [128][2*VDS] in phase 3
    float* QO = KV + KV_FL;         // Qps [64][QPS] in phase 1; Osm [32][OSS] in phase 3

    const int tid  = threadIdx.x;
    const int lane = tid & 31;
    const int wid  = tid >> 5;      // 0..15
    const int qgp  = wid >> 2;      // q-group 0..3 (8 q rows = 4 q-pairs)
    const int ks   = wid & 3;       // k-slice (phase 1) / tw (phase 3)
    const int qt   = blockIdx.x;
    const int bh   = blockIdx.y;

    const float* Qg = qg + (size_t)bh * SEQ * DH + (size_t)qt * QT * DH;
    const float* Kg = kg + (size_t)bh * SEQ * DH;
    const float* Vg = vg + (size_t)bh * SEQ * DH;
    float*       Og = og + (size_t)bh * SEQ * DH + (size_t)qt * QT * DH;

    // ---- stage Q transposed: Qps[d][q] = Q[q][d] (q-pairs contiguous) ----
#pragma unroll
    for (int i = 0; i < (QT * DH) / NTHR; i++) {
        int idx = i * NTHR + tid;
        int q = idx >> 6, d = idx & 63;
        QO[d * QPS + q] = Qg[idx];
    }

    // ======================= Phase 1: S = Q K^T =============================
    // warp (qgp, ks): 8 q x 64 k per tile; thread: 4 q-pairs x 2 k.
    // Q-pairs register-cached per 8-d chunk; K d-pairs split into f32x2 splats.
    const u64* Qp64 = (const u64*)QO;       // [d][16 qp], stride 17 u64
    const int k0 = ks * 64 + lane;

    for (int kt = 0; kt < SEQ / KTILE; kt++) {
        __syncthreads();
        // stage K tile row-major: Kt[kk][d], stride KDS
        const float2* Ksrc = (const float2*)(Kg + (size_t)kt * KTILE * DH);
#pragma unroll
        for (int i = 0; i < (KTILE * DH) / (2 * NTHR); i++) {
            int idx = i * NTHR + tid;       // float2 index
            int kk = idx >> 5, dp = idx & 31;
            *(float2*)&KV[kk * KDS + 2 * dp] = Ksrc[idx];
        }
        __syncthreads();

        u64 acc0[4], acc1[4];
#pragma unroll
        for (int qp = 0; qp < 4; qp++) { acc0[qp] = 0ull; acc1[qp] = 0ull; }

        const float* kp0 = &KV[k0 * KDS];
        const float* kp1 = &KV[(k0 + 32) * KDS];

#pragma unroll
        for (int dc = 0; dc < 8; dc++) {
            u64 qr[4][8];
#pragma unroll
            for (int j = 0; j < 8; j++)
#pragma unroll
                for (int qp = 0; qp < 4; qp++)
                    qr[qp][j] = Qp64[(dc * 8 + j) * 17 + qgp * 4 + qp];
#pragma unroll
            for (int m = 0; m < 4; m++) {
                float2 ka = *(const float2*)&kp0[dc * 8 + 2 * m];
                float2 kb = *(const float2*)&kp1[dc * 8 + 2 * m];
                u64 sa0 = dup2(ka.x), sa1 = dup2(ka.y);
                u64 sb0 = dup2(kb.x), sb1 = dup2(kb.y);
#pragma unroll
                for (int qp = 0; qp < 4; qp++) {
                    acc0[qp] = fma2(qr[qp][2 * m],     sa0, acc0[qp]);
                    acc0[qp] = fma2(qr[qp][2 * m + 1], sa1, acc0[qp]);
                    acc1[qp] = fma2(qr[qp][2 * m],     sb0, acc1[qp]);
                    acc1[qp] = fma2(qr[qp][2 * m + 1], sb1, acc1[qp]);
                }
            }
        }

        const int kgl = kt * KTILE + k0;
#pragma unroll
        for (int qp = 0; qp < 4; qp++) {
            *(u64*)&sc[kgl * SCS + qgp * 8 + 2 * qp]        = acc0[qp];
            *(u64*)&sc[(kgl + 32) * SCS + qgp * 8 + 2 * qp] = acc1[qp];
        }
    }
    __syncthreads();

    // ---- zero Osm (overlays Qps; Q no longer needed) ----
#pragma unroll
    for (int i = 0; i < 5; i++) {
        int idx = i * NTHR + tid;
        if (idx < QT * OSS) QO[idx] = 0.f;
    }

    // ======================= Phase 2: entmax-1.5 (Newton) ===================
    for (int rr = 0; rr < 2; rr++) {
        const int row = wid * 2 + rr;
        float x[32];
        float m = -1e30f;
#pragma unroll
        for (int j = 0; j < 32; j++) {
            x[j] = sc[(j * 32 + lane) * SCS + row] * 0.0625f;
            m = fmaxf(m, x[j]);
        }
#pragma unroll
        for (int o = 16; o; o >>= 1) m = fmaxf(m, __shfl_xor_sync(0xffffffffu, m, o));
#pragma unroll
        for (int j = 0; j < 32; j++) x[j] -= m;

        float tau = -1.0f;
#pragma unroll 1
        for (int it = 0; it < NEWTON; it++) {
            float s = 0.f, r = 0.f;
#pragma unroll
            for (int j = 0; j < 32; j++) {
                float t = fmaxf(x[j] - tau, 0.f);
                s = fmaf(t, t, s);
                r += t;
            }
#pragma unroll
            for (int o = 16; o; o >>= 1) {
                s += __shfl_xor_sync(0xffffffffu, s, o);
                r += __shfl_xor_sync(0xffffffffu, r, o);
            }
            tau += (s - 1.0f) / (2.0f * r);
        }
#pragma unroll
        for (int j = 0; j < 32; j++) {
            float t = fmaxf(x[j] - tau, 0.f);
            sc[(j * 32 + lane) * SCS + row] = t * t;
        }
    }

    // ======================= Phase 3: O = P V (outer product) ===============
    // warp (qgp, tw=ks): lanes = (ko = lane>>3) x (dl = lane&7).
    // thread: 4 q-pairs x 8 d (d = dl + 8j), k = ko + 32*tw + 4i per tile.
    const int ko = lane >> 3;
    const int dl = lane & 7;
    const int tw = ks;
    u64* Vd = (u64*)KV;                      // Vdup, row stride VDS u64

    u64 oacc[4][8];
#pragma unroll
    for (int qp = 0; qp < 4; qp++)
#pragma unroll
        for (int j = 0; j < 8; j++) oacc[qp][j] = 0ull;

    for (int vt = 0; vt < SEQ / VTILE; vt++) {
        __syncthreads();
        const float2* Vsrc = (const float2*)(Vg + (size_t)vt * VTILE * DH);
#pragma unroll
        for (int i = 0; i < (VTILE * DH) / (2 * NTHR); i++) {
            int idx = i * NTHR + tid;        // float2 index
            int kk = idx >> 5, dp = idx & 31;
            float2 v = Vsrc[idx];
            float2* dst = (float2*)&Vd[kk * VDS + 2 * dp];
            dst[0] = make_float2(v.x, v.x);
            dst[1] = make_float2(v.y, v.y);
        }
        __syncthreads();

        const float* scp = &sc[(vt * VTILE + ko + 32 * tw) * SCS + qgp * 8];
        const u64*   vp  = &Vd[(ko + 32 * tw) * VDS + dl];
#pragma unroll
        for (int i = 0; i < 8; i++) {
            u64 a0 = *(const u64*)(scp + 0);
            u64 a1 = *(const u64*)(scp + 2);
            u64 a2 = *(const u64*)(scp + 4);
            u64 a3 = *(const u64*)(scp + 6);
#pragma unroll
            for (int j = 0; j < 8; j++) {
                u64 b = vp[8 * j];
                oacc[0][j] = fma2(a0, b, oacc[0][j]);
                oacc[1][j] = fma2(a1, b, oacc[1][j]);
                oacc[2][j] = fma2(a2, b, oacc[2][j]);
                oacc[3][j] = fma2(a3, b, oacc[3][j]);
            }
            scp += 4 * SCS;
            vp  += 4 * VDS;
        }
    }

    // ---- reduce over ko (butterfly) then over tw warps (shared atomics) ----
#pragma unroll
    for (int qp = 0; qp < 4; qp++)
#pragma unroll
        for (int j = 0; j < 8; j++) {
            u64 v = oacc[qp][j];
            v = add2(v, __shfl_xor_sync(0xffffffffu, v, 8));
            v = add2(v, __shfl_xor_sync(0xffffffffu, v, 16));
            oacc[qp][j] = v;
        }

    float* Osm = QO;
    if (ko == 0) {
#pragma unroll
        for (int qp = 0; qp < 4; qp++)
#pragma unroll
            for (int j = 0; j < 8; j++) {
                float2 v = *(float2*)&oacc[qp][j];
                int d = dl + 8 * j;
                atomicAdd(&Osm[(qgp * 8 + 2 * qp) * OSS + d],     v.x);
                atomicAdd(&Osm[(qgp * 8 + 2 * qp + 1) * OSS + d], v.y);
            }
    }
    __syncthreads();

#pragma unroll
    for (int i = 0; i < (QT * DH) / NTHR; i++) {
        int idx = i * NTHR + tid;
        int q = idx >> 6, d = idx & 63;
        Og[idx] = Osm[q * OSS + d];
    }
}

extern "C" void kernel_launch(void* const* d_in, const int* in_sizes, int n_in,
                              void* d_out, int out_size)
{
    const float* q = (const float*)d_in[0];
    const float* k = (const float*)d_in[1];
    const float* v = (const float*)d_in[2];
    float* out = (float*)d_out;

    cudaFuncSetAttribute(attn_entmax15_kernel,
                         cudaFuncAttributeMaxDynamicSharedMemorySize, SMEM_BYTES);

    dim3 grid(SEQ / QT, 8 * 8);
    attn_entmax15_kernel<<<grid, NTHR, SMEM_BYTES>>>(q, k, v, out);
}

// round 6
// speedup vs baseline: 1.3895x; 1.0005x over previous
#include <cuda_runtime.h>

// entmax-1.5 attention, B=8 H=8 S=1024 D=64, fp32.
// Register-blocked f32x2 outer-product GEMMs; scores k-major in smem;
// Newton iteration for the entmax threshold.

#define SEQ   1024
#define DH    64
#define QT    32
#define NTHR  512
#define SCS   34      // sc float stride per k-row
#define KTILE 256
#define KDS   66      // Kt float stride per k-row
#define VTILE 128
#define VDS   68      // Vdup u64 stride per k-row (136 floats)
#define QPS   34      // Qps float stride per d
#define OSS   66      // Osm float stride per q-row
#define NEWTON 10

typedef unsigned long long u64;

#define SC_FL (SEQ * SCS)                 // 34816
#define KV_FL (VTILE * VDS * 2)           // 17408 (>= KTILE*KDS = 16896)
#define QO_FL (DH * QPS)                  // 2176  (>= 32*OSS = 2112)
#define SMEM_BYTES ((SC_FL + KV_FL + QO_FL) * 4)   // 217600

__device__ __forceinline__ u64 fma2(u64 a, u64 b, u64 c) {
    u64 d;
    asm("fma.rn.f32x2 %0, %1, %2, %3;" : "=l"(d) : "l"(a), "l"(b), "l"(c));
    return d;
}
__device__ __forceinline__ u64 add2(u64 a, u64 b) {
    u64 d;
    asm("add.rn.f32x2 %0, %1, %2;" : "=l"(d) : "l"(a), "l"(b));
    return d;
}
__device__ __forceinline__ u64 dup2(float v) {
    u64 d;
    asm("mov.b64 %0, {%1, %1};" : "=l"(d) : "f"(v));
    return d;
}

__global__ void __launch_bounds__(NTHR, 1)
attn_entmax15_kernel(const float* __restrict__ qg,
                     const float* __restrict__ kg,
                     const float* __restrict__ vg,
                     float* __restrict__ og)
{
    extern __shared__ float sm[];
    float* sc = sm;                 // [1024 k][SCS]  scores (k-major, q contiguous)
    float* KV = sm + SC_FL;         // Kt [256][KDS] in phase 1; Vdup [128][2*VDS] in phase 3
    float* QO = KV + KV_FL;         // Qps [64][QPS] in phase 1; Osm [32][OSS] in phase 3

    const int tid  = threadIdx.x;
    const int lane = tid & 31;
    const int wid  = tid >> 5;      // 0..15
    const int qgp  = wid >> 2;      // q-group 0..3 (8 q rows = 4 q-pairs)
    const int ks   = wid & 3;       // k-slice (phase 1) / tw (phase 3)
    const int qt   = blockIdx.x;
    const int bh   = blockIdx.y;

    const float* Qg = qg + (size_t)bh * SEQ * DH + (size_t)qt * QT * DH;
    const float* Kg = kg + (size_t)bh * SEQ * DH;
    const float* Vg = vg + (size_t)bh * SEQ * DH;
    float*       Og = og + (size_t)bh * SEQ * DH + (size_t)qt * QT * DH;

    // ---- stage Q transposed: Qps[d][q] = Q[q][d] (q-pairs contiguous) ----
#pragma unroll
    for (int i = 0; i < (QT * DH) / NTHR; i++) {
        int idx = i * NTHR + tid;
        int q = idx >> 6, d = idx & 63;
        QO[d * QPS + q] = Qg[idx];
    }

    // ======================= Phase 1: S = Q K^T =============================
    // warp (qgp, ks): 8 q x 64 k per tile; thread: 4 q-pairs x 2 k.
    // Q-pairs register-cached per 8-d chunk; K d-pairs split into f32x2 splats.
    const u64* Qp64 = (const u64*)QO;       // [d][16 qp], stride 17 u64
    const int k0 = ks * 64 + lane;

    for (int kt = 0; kt < SEQ / KTILE; kt++) {
        __syncthreads();
        // stage K tile row-major: Kt[kk][d], stride KDS
        const float2* Ksrc = (const float2*)(Kg + (size_t)kt * KTILE * DH);
#pragma unroll
        for (int i = 0; i < (KTILE * DH) / (2 * NTHR); i++) {
            int idx = i * NTHR + tid;       // float2 index
            int kk = idx >> 5, dp = idx & 31;
            *(float2*)&KV[kk * KDS + 2 * dp] = Ksrc[idx];
        }
        __syncthreads();

        u64 acc0[4], acc1[4];
#pragma unroll
        for (int qp = 0; qp < 4; qp++) { acc0[qp] = 0ull; acc1[qp] = 0ull; }

        const float* kp0 = &KV[k0 * KDS];
        const float* kp1 = &KV[(k0 + 32) * KDS];

#pragma unroll
        for (int dc = 0; dc < 8; dc++) {
            u64 qr[4][8];
#pragma unroll
            for (int j = 0; j < 8; j++)
#pragma unroll
                for (int qp = 0; qp < 4; qp++)
                    qr[qp][j] = Qp64[(dc * 8 + j) * 17 + qgp * 4 + qp];
#pragma unroll
            for (int m = 0; m < 4; m++) {
                float2 ka = *(const float2*)&kp0[dc * 8 + 2 * m];
                float2 kb = *(const float2*)&kp1[dc * 8 + 2 * m];
                u64 sa0 = dup2(ka.x), sa1 = dup2(ka.y);
                u64 sb0 = dup2(kb.x), sb1 = dup2(kb.y);
#pragma unroll
                for (int qp = 0; qp < 4; qp++) {
                    acc0[qp] = fma2(qr[qp][2 * m],     sa0, acc0[qp]);
                    acc0[qp] = fma2(qr[qp][2 * m + 1], sa1, acc0[qp]);
                    acc1[qp] = fma2(qr[qp][2 * m],     sb0, acc1[qp]);
                    acc1[qp] = fma2(qr[qp][2 * m + 1], sb1, acc1[qp]);
                }
            }
        }

        const int kgl = kt * KTILE + k0;
#pragma unroll
        for (int qp = 0; qp < 4; qp++) {
            *(u64*)&sc[kgl * SCS + qgp * 8 + 2 * qp]        = acc0[qp];
            *(u64*)&sc[(kgl + 32) * SCS + qgp * 8 + 2 * qp] = acc1[qp];
        }
    }
    __syncthreads();

    // ---- zero Osm (overlays Qps; Q no longer needed) ----
#pragma unroll
    for (int i = 0; i < 5; i++) {
        int idx = i * NTHR + tid;
        if (idx < QT * OSS) QO[idx] = 0.f;
    }

    // ======================= Phase 2: entmax-1.5 (Newton) ===================
    for (int rr = 0; rr < 2; rr++) {
        const int row = wid * 2 + rr;
        float x[32];
        float m = -1e30f;
#pragma unroll
        for (int j = 0; j < 32; j++) {
            x[j] = sc[(j * 32 + lane) * SCS + row] * 0.0625f;
            m = fmaxf(m, x[j]);
        }
#pragma unroll
        for (int o = 16; o; o >>= 1) m = fmaxf(m, __shfl_xor_sync(0xffffffffu, m, o));
#pragma unroll
        for (int j = 0; j < 32; j++) x[j] -= m;

        float tau = -1.0f;
#pragma unroll 1
        for (int it = 0; it < NEWTON; it++) {
            float s = 0.f, r = 0.f;
#pragma unroll
            for (int j = 0; j < 32; j++) {
                float t = fmaxf(x[j] - tau, 0.f);
                s = fmaf(t, t, s);
                r += t;
            }
#pragma unroll
            for (int o = 16; o; o >>= 1) {
                s += __shfl_xor_sync(0xffffffffu, s, o);
                r += __shfl_xor_sync(0xffffffffu, r, o);
            }
            tau += (s - 1.0f) / (2.0f * r);
        }
#pragma unroll
        for (int j = 0; j < 32; j++) {
            float t = fmaxf(x[j] - tau, 0.f);
            sc[(j * 32 + lane) * SCS + row] = t * t;
        }
    }

    // ======================= Phase 3: O = P V (outer product) ===============
    // warp (qgp, tw=ks): lanes = (ko = lane>>3) x (dl = lane&7).
    // thread: 4 q-pairs x 8 d (d = dl + 8j), k = ko + 32*tw + 4i per tile.
    const int ko = lane >> 3;
    const int dl = lane & 7;
    const int tw = ks;
    u64* Vd = (u64*)KV;                      // Vdup, row stride VDS u64

    u64 oacc[4][8];
#pragma unroll
    for (int qp = 0; qp < 4; qp++)
#pragma unroll
        for (int j = 0; j < 8; j++) oacc[qp][j] = 0ull;

    for (int vt = 0; vt < SEQ / VTILE; vt++) {
        __syncthreads();
        const float2* Vsrc = (const float2*)(Vg + (size_t)vt * VTILE * DH);
#pragma unroll
        for (int i = 0; i < (VTILE * DH) / (2 * NTHR); i++) {
            int idx = i * NTHR + tid;        // float2 index
            int kk = idx >> 5, dp = idx & 31;
            float2 v = Vsrc[idx];
            float2* dst = (float2*)&Vd[kk * VDS + 2 * dp];
            dst[0] = make_float2(v.x, v.x);
            dst[1] = make_float2(v.y, v.y);
        }
        __syncthreads();

        const float* scp = &sc[(vt * VTILE + ko + 32 * tw) * SCS + qgp * 8];
        const u64*   vp  = &Vd[(ko + 32 * tw) * VDS + dl];
#pragma unroll
        for (int i = 0; i < 8; i++) {
            u64 a0 = *(const u64*)(scp + 0);
            u64 a1 = *(const u64*)(scp + 2);
            u64 a2 = *(const u64*)(scp + 4);
            u64 a3 = *(const u64*)(scp + 6);
#pragma unroll
            for (int j = 0; j < 8; j++) {
                u64 b = vp[8 * j];
                oacc[0][j] = fma2(a0, b, oacc[0][j]);
                oacc[1][j] = fma2(a1, b, oacc[1][j]);
                oacc[2][j] = fma2(a2, b, oacc[2][j]);
                oacc[3][j] = fma2(a3, b, oacc[3][j]);
            }
            scp += 4 * SCS;
            vp  += 4 * VDS;
        }
    }

    // ---- reduce over ko (butterfly) then over tw warps (shared atomics) ----
#pragma unroll
    for (int qp = 0; qp < 4; qp++)
#pragma unroll
        for (int j = 0; j < 8; j++) {
            u64 v = oacc[qp][j];
            v = add2(v, __shfl_xor_sync(0xffffffffu, v, 8));
            v = add2(v, __shfl_xor_sync(0xffffffffu, v, 16));
            oacc[qp][j] = v;
        }

    float* Osm = QO;
    if (ko == 0) {
#pragma unroll
        for (int qp = 0; qp < 4; qp++)
#pragma unroll
            for (int j = 0; j < 8; j++) {
                float2 v = *(float2*)&oacc[qp][j];
                int d = dl + 8 * j;
                atomicAdd(&Osm[(qgp * 8 + 2 * qp) * OSS + d],     v.x);
                atomicAdd(&Osm[(qgp * 8 + 2 * qp + 1) * OSS + d], v.y);
            }
    }
    __syncthreads();

#pragma unroll
    for (int i = 0; i < (QT * DH) / NTHR; i++) {
        int idx = i * NTHR + tid;
        int q = idx >> 6, d = idx & 63;
        Og[idx] = Osm[q * OSS + d];
    }
}

extern "C" void kernel_launch(void* const* d_in, const int* in_sizes, int n_in,
                              void* d_out, int out_size)
{
    const float* q = (const float*)d_in[0];
    const float* k = (const float*)d_in[1];
    const float* v = (const float*)d_in[2];
    float* out = (float*)d_out;

    cudaFuncSetAttribute(attn_entmax15_kernel,
                         cudaFuncAttributeMaxDynamicSharedMemorySize, SMEM_BYTES);

    dim3 grid(SEQ / QT, 8 * 8);
    attn_entmax15_kernel<<<grid, NTHR, SMEM_BYTES>>>(q, k, v, out);
}

// round 9
// speedup vs baseline: 2.2959x; 1.6524x over previous
#include <cuda_runtime.h>

// entmax-1.5 attention, B=8 H=8 S=1024 D=64, fp32.
// Both GEMMs on mma.sync.m16n8k16 (bf16 hi/lo split, fp32 accumulate).
// S fp32 q-major in smem; entmax Newton; P packed bf16 hi/lo in place.

#define SEQ  1024
#define DH   64
#define QT   32
#define NTHR 512
#define PS   1036     // S/P row stride (words)
#define KVS  68       // K/V tile row stride (words)  [multiple of 4: STS.128-aligned]
#define QS   68       // Q row stride (words)
#define OSS  66       // Osm row stride (floats)
#define KT   256      // staging tile rows
#define NEWTON 10

typedef unsigned int u32;

#define S_WORDS  (QT * PS)       // 33152
#define KV_WORDS (KT * KVS)      // 17408
#define Q_WORDS  (QT * QS)       // 2176 (also Osm: 32*66=2112 floats)
#define SMEM_BYTES ((S_WORDS + KV_WORDS + Q_WORDS) * 4)   // 210944

__device__ __forceinline__ u32 prmt(u32 a, u32 b, u32 s) {
    u32 d; asm("prmt.b32 %0, %1, %2, %3;" : "=r"(d) : "r"(a), "r"(b), "r"(s)); return d;
}
__device__ __forceinline__ u32 cvt2(float hi, float lo) {   // {bf16(hi)|bf16(lo)}
    u32 d; asm("cvt.rn.bf16x2.f32 %0, %1, %2;" : "=r"(d) : "f"(hi), "f"(lo)); return d;
}
// pack elements x0,x1 -> w0={L0 hi16, H0 lo16}, w1={L1, H1}
__device__ __forceinline__ uint2 pack2(float x0, float x1) {
    u32 Hp = cvt2(x1, x0);
    float h0 = __uint_as_float(Hp << 16);
    float h1 = __uint_as_float(Hp & 0xffff0000u);
    u32 Lp = cvt2(x1 - h1, x0 - h0);
    return make_uint2(prmt(Hp, Lp, 0x5410), prmt(Hp, Lp, 0x7632));
}
__device__ __forceinline__ u32 pack1(float x) {
    u32 Hp = cvt2(x, x);
    float h = __uint_as_float(Hp << 16);
    u32 Lp = cvt2(0.f, x - h);
    return prmt(Hp, Lp, 0x5410);
}
__device__ __forceinline__ void mma16816(float* c, const u32* a, u32 b0, u32 b1) {
    asm volatile("mma.sync.aligned.m16n8k16.row.col.f32.bf16.bf16.f32 "
        "{%0,%1,%2,%3}, {%4,%5,%6,%7}, {%8,%9}, {%0,%1,%2,%3};"
        : "+f"(c[0]), "+f"(c[1]), "+f"(c[2]), "+f"(c[3])
        : "r"(a[0]), "r"(a[1]), "r"(a[2]), "r"(a[3]), "r"(b0), "r"(b1));
}
// A frag (16x16) hi+lo from packed plane; p = &buf[row0*stride + kw]
__device__ __forceinline__ void ldA(const u32* p, int stride, u32* ah, u32* al) {
    uint2 w;
    w = *(const uint2*)(p);
    ah[0] = prmt(w.x, w.y, 0x5410); al[0] = prmt(w.x, w.y, 0x7632);
    w = *(const uint2*)(p + 8 * stride);
    ah[1] = prmt(w.x, w.y, 0x5410); al[1] = prmt(w.x, w.y, 0x7632);
    w = *(const uint2*)(p + 8);
    ah[2] = prmt(w.x, w.y, 0x5410); al[2] = prmt(w.x, w.y, 0x7632);
    w = *(const uint2*)(p + 8 * stride + 8);
    ah[3] = prmt(w.x, w.y, 0x5410); al[3] = prmt(w.x, w.y, 0x7632);
}
// stage a 256x64 fp32 tile as packed bf16 hi/lo (8 float4 per thread)
__device__ __forceinline__ void stage_tile(const float4* src, u32* dst, int tid) {
#pragma unroll
    for (int i = 0; i < 8; i++) {
        int idx = i * NTHR + tid;
        float4 f = src[idx];
        int row = idx >> 4, d4 = idx & 15;
        uint2 w01 = pack2(f.x, f.y);
        uint2 w23 = pack2(f.z, f.w);
        *(uint4*)&dst[row * KVS + 4 * d4] = make_uint4(w01.x, w01.y, w23.x, w23.y);
    }
}

__global__ void __launch_bounds__(NTHR, 1)
attn_entmax15_mma(const float* __restrict__ qg,
                  const float* __restrict__ kg,
                  const float* __restrict__ vg,
                  float* __restrict__ og)
{
    extern __shared__ u32 sm[];
    u32* S  = sm;                    // [32][PS]  fp32 scores, later packed P
    u32* KV = sm + S_WORDS;          // [256][KVS] packed K / V tile
    u32* Qb = KV + KV_WORDS;         // [32][QS] packed Q, later Osm f32

    const int tid  = threadIdx.x;
    const int lane = tid & 31;
    const int wid  = tid >> 5;       // 0..15
    const int g    = lane >> 2;      // 0..7
    const int t    = lane & 3;       // 0..3
    const int qt   = blockIdx.x;
    const int bh   = blockIdx.y;

    const float* Qg = qg + (size_t)bh * SEQ * DH + (size_t)qt * QT * DH;
    const float* Kg = kg + (size_t)bh * SEQ * DH;
    const float* Vg = vg + (size_t)bh * SEQ * DH;
    float*       Og = og + (size_t)bh * SEQ * DH + (size_t)qt * QT * DH;

    // ---- stage Q packed (one float4 per thread) ----
    {
        float4 f = ((const float4*)Qg)[tid];
        int row = tid >> 4, d4 = tid & 15;
        uint2 w01 = pack2(f.x, f.y);
        uint2 w23 = pack2(f.z, f.w);
        *(uint4*)&Qb[row * QS + 4 * d4] = make_uint4(w01.x, w01.y, w23.x, w23.y);
    }

    // ======================= GEMM1: S = Q K^T ===============================
    float* Sf = (float*)S;
    for (int kt2 = 0; kt2 < 4; kt2++) {
        __syncthreads();
        stage_tile((const float4*)Kg + kt2 * 4096, KV, tid);
        __syncthreads();

        float c[2][2][4];
#pragma unroll
        for (int m = 0; m < 2; m++)
#pragma unroll
            for (int n = 0; n < 2; n++)
#pragma unroll
                for (int r = 0; r < 4; r++) c[m][n][r] = 0.f;

#pragma unroll
        for (int ks = 0; ks < 4; ks++) {
            const int kw = ks * 16 + 2 * t;
            u32 ah[2][4], al[2][4];
            ldA(Qb + g * QS + kw, QS, ah[0], al[0]);
            ldA(Qb + (16 + g) * QS + kw, QS, ah[1], al[1]);
#pragma unroll
            for (int n = 0; n < 2; n++) {
                const u32* p = KV + (wid * 16 + n * 8 + g) * KVS + kw;
                uint2 w0 = *(const uint2*)p;
                uint2 w1 = *(const uint2*)(p + 8);
                u32 b0h = prmt(w0.x, w0.y, 0x5410), b0l = prmt(w0.x, w0.y, 0x7632);
                u32 b1h = prmt(w1.x, w1.y, 0x5410), b1l = prmt(w1.x, w1.y, 0x7632);
#pragma unroll
                for (int m = 0; m < 2; m++) {
                    mma16816(c[m][n], ah[m], b0h, b1h);
                    mma16816(c[m][n], ah[m], b0l, b1l);
                    mma16816(c[m][n], al[m], b0h, b1h);
                }
            }
        }
#pragma unroll
        for (int m = 0; m < 2; m++)
#pragma unroll
            for (int n = 0; n < 2; n++) {
                int row = m * 16 + g;
                int col = kt2 * 256 + wid * 16 + n * 8 + 2 * t;
                *(float2*)&Sf[row * PS + col]       = make_float2(c[m][n][0], c[m][n][1]);
                *(float2*)&Sf[(row + 8) * PS + col] = make_float2(c[m][n][2], c[m][n][3]);
            }
    }
    __syncthreads();

    // ---- zero Osm (overlays Qb; Q is dead) ----
    float* Osm = (float*)Qb;
#pragma unroll
    for (int i = 0; i < 5; i++) {
        int idx = i * NTHR + tid;
        if (idx < QT * OSS) Osm[idx] = 0.f;
    }

    // ======================= entmax-1.5 (Newton) ============================
    for (int rr = 0; rr < 2; rr++) {
        const int row = wid * 2 + rr;
        float x[32];
        float m = -1e30f;
#pragma unroll
        for (int j = 0; j < 32; j++) {
            x[j] = Sf[row * PS + j * 32 + lane] * 0.0625f;
            m = fmaxf(m, x[j]);
        }
#pragma unroll
        for (int o = 16; o; o >>= 1) m = fmaxf(m, __shfl_xor_sync(0xffffffffu, m, o));
#pragma unroll
        for (int j = 0; j < 32; j++) x[j] -= m;

        float tau = -1.0f;
#pragma unroll 1
        for (int it = 0; it < NEWTON; it++) {
            float s = 0.f, r = 0.f;
#pragma unroll
            for (int j = 0; j < 32; j++) {
                float u = fmaxf(x[j] - tau, 0.f);
                s = fmaf(u, u, s);
                r += u;
            }
#pragma unroll
            for (int o = 16; o; o >>= 1) {
                s += __shfl_xor_sync(0xffffffffu, s, o);
                r += __shfl_xor_sync(0xffffffffu, r, o);
            }
            tau += (s - 1.0f) / (2.0f * r);
        }
#pragma unroll
        for (int j = 0; j < 32; j++) {
            float u = fmaxf(x[j] - tau, 0.f);
            S[row * PS + j * 32 + lane] = pack1(u * u);   // in-place packed P
        }
    }

    // ======================= GEMM2: O = P V =================================
    const int ng = wid >> 3;     // d half (0..1)
    const int kh = wid & 7;      // k slice (0..7)
    float oc[2][4][4];
#pragma unroll
    for (int m = 0; m < 2; m++)
#pragma unroll
        for (int nf = 0; nf < 4; nf++)
#pragma unroll
            for (int r = 0; r < 4; r++) oc[m][nf][r] = 0.f;

    for (int vt = 0; vt < 4; vt++) {
        __syncthreads();
        stage_tile((const float4*)Vg + vt * 4096, KV, tid);
        __syncthreads();

#pragma unroll
        for (int s2 = 0; s2 < 2; s2++) {
            const int ksl = kh * 2 + s2;            // kstep within tile (0..15)
            const int kw  = vt * 256 + ksl * 16 + 2 * t;
            u32 ah[2][4], al[2][4];
            ldA(S + g * PS + kw, PS, ah[0], al[0]);
            ldA(S + (16 + g) * PS + kw, PS, ah[1], al[1]);
#pragma unroll
            for (int nf = 0; nf < 4; nf++) {
                const int d = ng * 32 + nf * 8 + g;
                const u32* p = KV + (ksl * 16 + 2 * t) * KVS + d;
                u32 w0 = p[0], w1 = p[KVS];
                u32 w2 = p[8 * KVS], w3 = p[9 * KVS];
                u32 b0h = prmt(w0, w1, 0x5410), b0l = prmt(w0, w1, 0x7632);
                u32 b1h = prmt(w2, w3, 0x5410), b1l = prmt(w2, w3, 0x7632);
#pragma unroll
                for (int m = 0; m < 2; m++) {
                    mma16816(oc[m][nf], ah[m], b0h, b1h);
                    mma16816(oc[m][nf], ah[m], b0l, b1l);
                    mma16816(oc[m][nf], al[m], b0h, b1h);
                }
            }
        }
    }

    // ---- reduce k-slices into Osm ----
#pragma unroll
    for (int m = 0; m < 2; m++)
#pragma unroll
        for (int nf = 0; nf < 4; nf++) {
            int row = m * 16 + g;
            int d = ng * 32 + nf * 8 + 2 * t;
            atomicAdd(&Osm[row * OSS + d],           oc[m][nf][0]);
            atomicAdd(&Osm[row * OSS + d + 1],       oc[m][nf][1]);
            atomicAdd(&Osm[(row + 8) * OSS + d],     oc[m][nf][2]);
            atomicAdd(&Osm[(row + 8) * OSS + d + 1], oc[m][nf][3]);
        }
    __syncthreads();

#pragma unroll
    for (int i = 0; i < (QT * DH) / NTHR; i++) {
        int idx = i * NTHR + tid;
        int q = idx >> 6, d = idx & 63;
        Og[idx] = Osm[q * OSS + d];
    }
}

extern "C" void kernel_launch(void* const* d_in, const int* in_sizes, int n_in,
                              void* d_out, int out_size)
{
    const float* q = (const float*)d_in[0];
    const float* k = (const float*)d_in[1];
    const float* v = (const float*)d_in[2];
    float* out = (float*)d_out;

    cudaFuncSetAttribute(attn_entmax15_mma,
                         cudaFuncAttributeMaxDynamicSharedMemorySize, SMEM_BYTES);

    dim3 grid(SEQ / QT, 8 * 8);
    attn_entmax15_mma<<<grid, NTHR, SMEM_BYTES>>>(q, k, v, out);
}